// round 14
// baseline (speedup 1.0000x reference)
#include <cuda_runtime.h>
#include <cuda_fp16.h>
#include <cstdint>

#define NTOK 65536
#define KCB  8192
#define DDIM 64
#define DECAYF 0.9f
#define EPSF 1e-5f

// ---- scratch (no allocation allowed) ----
__device__ float g_cnorm[KCB];
__device__ int   g_token[NTOK];
__device__ float g_counts[KCB];
__device__ float g_embed_sum[KCB * DDIM];
__device__ float g_qerr;
__device__ float g_nsum;
// packed fp16x2 split codebook, k-pair-major: g_w2t[kp][c]
__device__ __align__(16) uint32_t g_w2t[(size_t)64 * KCB];

// ================= helpers =================
__device__ __forceinline__ uint32_t smem_u32(const void* p) {
    uint32_t a;
    asm("{ .reg .u64 t; cvta.to.shared.u64 t, %1; cvt.u32.u64 %0, t; }" : "=r"(a) : "l"(p));
    return a;
}
__device__ __forceinline__ void cp16(uint32_t dst, const void* src) {
    asm volatile("cp.async.ca.shared.global [%0], [%1], 16;" :: "r"(dst), "l"(src));
}
__device__ __forceinline__ uint32_t packh2(float a, float b) {
    __half2 h = __halves2half2(__float2half_rn(a), __float2half_rn(b));
    return *reinterpret_cast<uint32_t*>(&h);
}
// no memory clobber: MMA touches only registers
__device__ __forceinline__ void mma16(float* c, const uint32_t* a, uint32_t b0, uint32_t b1) {
    asm volatile("mma.sync.aligned.m16n8k16.row.col.f32.f16.f16.f32 "
        "{%0,%1,%2,%3},{%4,%5,%6,%7},{%8,%9},{%0,%1,%2,%3};"
        : "+f"(c[0]), "+f"(c[1]), "+f"(c[2]), "+f"(c[3])
        : "r"(a[0]), "r"(a[1]), "r"(a[2]), "r"(a[3]), "r"(b0), "r"(b1));
}

// ================= small kernels =================
__global__ void k_zero() {
    int i = blockIdx.x * blockDim.x + threadIdx.x;
    if (i < KCB * DDIM) g_embed_sum[i] = 0.0f;
    if (i < KCB)        g_counts[i]    = 0.0f;
    if (i == 0) { g_qerr = 0.0f; g_nsum = 0.0f; }
}

__global__ void k_cnorm(const float* __restrict__ w) {
    int warp = (blockIdx.x * blockDim.x + threadIdx.x) >> 5;
    int lane = threadIdx.x & 31;
    if (warp >= KCB) return;
    float v0 = w[warp * DDIM + lane];
    float v1 = w[warp * DDIM + 32 + lane];
    float s = v0 * v0 + v1 * v1;
    #pragma unroll
    for (int o = 16; o; o >>= 1) s += __shfl_xor_sync(0xffffffffu, s, o);
    if (lane == 0) g_cnorm[warp] = s;
}

// build g_w2t: hi pairs (kp<32) and lo pairs (kp>=32), code-contiguous rows
__global__ void k_prep(const float* __restrict__ w) {
    int i = blockIdx.x * blockDim.x + threadIdx.x;
    if (i >= 64 * KCB) return;
    int kp = i >> 13, c = i & (KCB - 1);
    int d = 2 * (kp & 31);
    float x0 = w[(size_t)c * DDIM + d];
    float x1 = w[(size_t)c * DDIM + d + 1];
    float h0 = __half2float(__float2half_rn(x0));
    float h1 = __half2float(__float2half_rn(x1));
    g_w2t[i] = (kp < 32) ? packh2(x0, x1) : packh2(x0 - h0, x1 - h1);
}

// ================= main tensor-core kernel (fp16x3, A-resident, 2 CTAs/SM) =================
static constexpr int AST   = 68;                       // A row stride (uint32)
static constexpr int BST   = 72;                       // B kp-row stride (uint32)
static constexpr int SM_A  = 0;                        // 128*68*4 = 34816
static constexpr int SM_B  = 34816;
static constexpr int B_BUF = 64 * BST * 4;             // 18432
static constexpr int SMEM_TC = SM_B + 3 * B_BUF;       // 90112

__global__ __launch_bounds__(256, 2) void k_main_tc(const float* __restrict__ z) {
    extern __shared__ char smem[];
    uint32_t* Au = (uint32_t*)(smem + SM_A);
    uint32_t* Bu = (uint32_t*)(smem + SM_B);
    const uint32_t sbB = smem_u32(Bu);

    const int tid  = threadIdx.x;
    const int lane = tid & 31, wid = tid >> 5;
    const int g    = lane >> 2, tg = lane & 3;
    const int wr   = wid & 3,  wc = wid >> 2;          // 4 token-rows x 2 code-cols
    const int tok0 = blockIdx.x * 128;

    // ---- prologue prefetch of B tiles 0,1 (each 64 codes x 64 kp) ----
    #pragma unroll
    for (int pt = 0; pt < 2; pt++) {
        const uint32_t dstb = sbB + (uint32_t)pt * B_BUF;
        const uint32_t* srcb = g_w2t + pt * 64;
        #pragma unroll
        for (int i = 0; i < 4; i++) {
            int q = i * 256 + tid;                     // 1024 x 16B
            int kp = q >> 4, seg = q & 15;
            cp16(dstb + (uint32_t)(kp * BST + seg * 4) * 4,
                 srcb + (size_t)kp * KCB + seg * 4);
        }
        asm volatile("cp.async.commit_group;");
    }

    // ---- stage A: fp16 split, kp-major: hi kp 0..31, lo kp 32..63 ----
    #pragma unroll
    for (int i = 0; i < 8; i++) {
        int q = i * 256 + tid;                         // 2048 float4
        int row = q >> 4, c4 = q & 15;
        float4 v = *(const float4*)(z + (size_t)(tok0 + row) * DDIM + c4 * 4);
        float hx = __half2float(__float2half_rn(v.x));
        float hy = __half2float(__float2half_rn(v.y));
        float hz = __half2float(__float2half_rn(v.z));
        float hw = __half2float(__float2half_rn(v.w));
        uint32_t* dst = Au + row * AST + 2 * c4;
        dst[0]  = packh2(v.x, v.y);
        dst[1]  = packh2(v.z, v.w);
        dst[32] = packh2(v.x - hx, v.y - hy);
        dst[33] = packh2(v.z - hz, v.w - hw);
    }
    __syncthreads();

    // ---- load ALL A fragments to registers (invariant across tiles) ----
    uint32_t Ah[4][2][4], Al[4][2][4];                 // [j][m][reg]
    {
        const uint32_t* arow = Au + (wr * 32 + g) * AST;
        #pragma unroll
        for (int j = 0; j < 4; j++) {
            #pragma unroll
            for (int m = 0; m < 2; m++) {
                const uint32_t* aph = arow + m * 16 * AST + 8 * j + tg;
                Ah[j][m][0] = aph[0];
                Ah[j][m][1] = aph[8 * AST];
                Ah[j][m][2] = aph[4];
                Ah[j][m][3] = aph[8 * AST + 4];
                const uint32_t* apl = aph + 32;
                Al[j][m][0] = apl[0];
                Al[j][m][1] = apl[8 * AST];
                Al[j][m][2] = apl[4];
                Al[j][m][3] = apl[8 * AST + 4];
            }
        }
    }

    float bv[4];  int bix[4];
    #pragma unroll
    for (int r = 0; r < 4; r++) { bv[r] = 3.4e38f; bix[r] = 0; }

    for (int t = 0; t < 128; t++) {
        if (t < 127) asm volatile("cp.async.wait_group 1;");
        else         asm volatile("cp.async.wait_group 0;");
        __syncthreads();
        if (t + 2 < 128) {
            const uint32_t dstb = sbB + (uint32_t)((t + 2) % 3) * B_BUF;
            const uint32_t* srcb = g_w2t + (t + 2) * 64;
            #pragma unroll
            for (int i = 0; i < 4; i++) {
                int q = i * 256 + tid;
                int kp = q >> 4, seg = q & 15;
                cp16(dstb + (uint32_t)(kp * BST + seg * 4) * 4,
                     srcb + (size_t)kp * KCB + seg * 4);
            }
            asm volatile("cp.async.commit_group;");
        }

        const uint32_t* B = Bu + (t % 3) * (64 * BST);
        float acc[2][4][4];
        #pragma unroll
        for (int m = 0; m < 2; m++)
            #pragma unroll
            for (int nt = 0; nt < 4; nt++)
                #pragma unroll
                for (int c = 0; c < 4; c++) acc[m][nt][c] = 0.0f;

        // per j: load all 16 B fragments, then issue 24 MMAs rotated across
        // all 8 accumulator chains (reuse gap = 8 MMAs >> HMMA latency).
        // Per-accumulator term order (hi*hi, hi*lo, lo*hi per j) is identical
        // to prior rounds -> bit-identical results.
        #pragma unroll
        for (int j = 0; j < 4; j++) {
            uint32_t bh[4][2], bl[4][2];
            const uint32_t* brow = B + (8 * j + tg) * BST + wc * 32 + g;
            #pragma unroll
            for (int nt = 0; nt < 4; nt++) {
                const uint32_t* bp = brow + nt * 8;
                bh[nt][0] = bp[0];
                bh[nt][1] = bp[4 * BST];
                bl[nt][0] = bp[32 * BST];
                bl[nt][1] = bp[36 * BST];
            }
            #pragma unroll
            for (int nt = 0; nt < 4; nt++)
                mma16(acc[0][nt], Ah[j][0], bh[nt][0], bh[nt][1]);
            #pragma unroll
            for (int nt = 0; nt < 4; nt++)
                mma16(acc[1][nt], Ah[j][1], bh[nt][0], bh[nt][1]);
            #pragma unroll
            for (int nt = 0; nt < 4; nt++)
                mma16(acc[0][nt], Ah[j][0], bl[nt][0], bl[nt][1]);
            #pragma unroll
            for (int nt = 0; nt < 4; nt++)
                mma16(acc[1][nt], Ah[j][1], bl[nt][0], bl[nt][1]);
            #pragma unroll
            for (int nt = 0; nt < 4; nt++)
                mma16(acc[0][nt], Al[j][0], bh[nt][0], bh[nt][1]);
            #pragma unroll
            for (int nt = 0; nt < 4; nt++)
                mma16(acc[1][nt], Al[j][1], bh[nt][0], bh[nt][1]);
        }

        // epilogue: dist = cn - 2*dot, running argmin (ascending codes = first-min)
        const int cb = t * 64;
        #pragma unroll
        for (int nt = 0; nt < 4; nt++) {
            const int col = cb + wc * 32 + nt * 8 + 2 * tg;
            const float2 c2 = __ldg((const float2*)(g_cnorm + col));
            #pragma unroll
            for (int m = 0; m < 2; m++) {
                #pragma unroll
                for (int h = 0; h < 2; h++) {
                    const int r = m * 2 + h;
                    float d0 = fmaf(-2.0f, acc[m][nt][h * 2 + 0], c2.x);
                    float d1 = fmaf(-2.0f, acc[m][nt][h * 2 + 1], c2.y);
                    if (d0 < bv[r]) { bv[r] = d0; bix[r] = col; }
                    if (d1 < bv[r]) { bv[r] = d1; bix[r] = col + 1; }
                }
            }
        }
    }

    // combine across quad lanes (same token rows), tie-break smaller index
    #pragma unroll
    for (int r = 0; r < 4; r++) {
        float v = bv[r]; int ix = bix[r];
        #pragma unroll
        for (int o = 1; o < 4; o <<= 1) {
            float v2 = __shfl_xor_sync(0xffffffffu, v, o);
            int   i2 = __shfl_xor_sync(0xffffffffu, ix, o);
            if (v2 < v || (v2 == v && i2 < ix)) { v = v2; ix = i2; }
        }
        bv[r] = v; bix[r] = ix;
    }
    __syncthreads();
    float* sv = (float*)Bu;
    int*   si = (int*)(Bu + 256);
    if (tg == 0) {
        #pragma unroll
        for (int m = 0; m < 2; m++)
            #pragma unroll
            for (int h = 0; h < 2; h++) {
                int row = wr * 32 + m * 16 + g + 8 * h;
                sv[wc * 128 + row] = bv[m * 2 + h];
                si[wc * 128 + row] = bix[m * 2 + h];
            }
    }
    __syncthreads();
    if (tid < 128) {
        float v0 = sv[tid], v1 = sv[128 + tid];
        int   i0 = si[tid], i1 = si[128 + tid];
        g_token[tok0 + tid] = (v1 < v0 || (v1 == v0 && i1 < i0)) ? i1 : i0;
    }
}

// ---------------- scatter: counts, embed_sum, quant error ----------------
__global__ void k_scatter(const float* __restrict__ z, const float* __restrict__ w) {
    __shared__ float qs[8];
    int warp = threadIdx.x >> 5;
    int lane = threadIdx.x & 31;
    int n = blockIdx.x * 8 + warp;
    int k = g_token[n];
    float z0 = z[(size_t)n * DDIM + lane];
    float z1 = z[(size_t)n * DDIM + 32 + lane];
    float w0 = w[(size_t)k * DDIM + lane];
    float w1 = w[(size_t)k * DDIM + 32 + lane];
    atomicAdd(&g_embed_sum[k * DDIM + lane], z0);
    atomicAdd(&g_embed_sum[k * DDIM + 32 + lane], z1);
    float d0 = w0 - z0, d1 = w1 - z1;
    float s = d0 * d0 + d1 * d1;
    #pragma unroll
    for (int o = 16; o; o >>= 1) s += __shfl_xor_sync(0xffffffffu, s, o);
    if (lane == 0) { qs[warp] = s; atomicAdd(&g_counts[k], 1.0f); }
    __syncthreads();
    if (threadIdx.x == 0) {
        float t = 0.0f;
        #pragma unroll
        for (int i = 0; i < 8; i++) t += qs[i];
        atomicAdd(&g_qerr, t);
    }
}

__global__ void k_ema1(const float* __restrict__ cs, float* __restrict__ out) {
    __shared__ float red[256];
    int k = blockIdx.x * blockDim.x + threadIdx.x;
    float ncs = cs[k] * DECAYF + (1.0f - DECAYF) * g_counts[k];
    out[1 + KCB * DDIM + k] = ncs;
    red[threadIdx.x] = ncs;
    __syncthreads();
    for (int s = 128; s; s >>= 1) {
        if (threadIdx.x < s) red[threadIdx.x] += red[threadIdx.x + s];
        __syncthreads();
    }
    if (threadIdx.x == 0) atomicAdd(&g_nsum, red[0]);
}

__global__ void k_ema2(const float* __restrict__ ea, float* __restrict__ out) {
    int i = blockIdx.x * blockDim.x + threadIdx.x;
    if (i < KCB * DDIM) {
        float nea = ea[i] * DECAYF + (1.0f - DECAYF) * g_embed_sum[i];
        out[1 + KCB * DDIM + KCB + i] = nea;
        int k = i >> 6;
        float ncs = out[1 + KCB * DDIM + k];
        float n = g_nsum;
        float smoothed = (ncs + EPSF) / (n + (float)KCB * EPSF) * n;
        out[1 + i] = nea / smoothed;
    }
    if (i == 0) out[0] = g_qerr / (float)NTOK;
}

extern "C" void kernel_launch(void* const* d_in, const int* in_sizes, int n_in,
                              void* d_out, int out_size) {
    const float* z  = (const float*)d_in[0];
    const float* w  = (const float*)d_in[1];
    const float* cs = (const float*)d_in[2];
    const float* ea = (const float*)d_in[3];
    float* out = (float*)d_out;

    cudaFuncSetAttribute(k_main_tc, cudaFuncAttributeMaxDynamicSharedMemorySize, SMEM_TC);

    k_zero<<<(KCB * DDIM + 255) / 256, 256>>>();
    k_cnorm<<<KCB / 8, 256>>>(w);
    k_prep<<<(64 * KCB + 255) / 256, 256>>>(w);
    k_main_tc<<<NTOK / 128, 256, SMEM_TC>>>(z);
    k_scatter<<<NTOK / 8, 256>>>(z, w);
    k_ema1<<<KCB / 256, 256>>>(cs, out);
    k_ema2<<<(KCB * DDIM + 255) / 256, 256>>>(ea, out);
}

// round 15
// speedup vs baseline: 1.1263x; 1.1263x over previous
#include <cuda_runtime.h>
#include <cuda_fp16.h>
#include <cstdint>

#define NTOK 65536
#define KCB  8192
#define DDIM 64
#define DECAYF 0.9f
#define EPSF 1e-5f

// ---- scratch (no allocation allowed) ----
__device__ float g_cnorm[KCB];
__device__ unsigned long long g_keys[NTOK];   // packed (ordered dist, code)
__device__ float g_counts[KCB];
__device__ float g_embed_sum[KCB * DDIM];
__device__ float g_qerr;
__device__ float g_nsum;
// packed fp16x2 split codebook, k-pair-major: g_w2t[kp][c]
__device__ __align__(16) uint32_t g_w2t[(size_t)64 * KCB];

// ================= helpers =================
__device__ __forceinline__ uint32_t smem_u32(const void* p) {
    uint32_t a;
    asm("{ .reg .u64 t; cvta.to.shared.u64 t, %1; cvt.u32.u64 %0, t; }" : "=r"(a) : "l"(p));
    return a;
}
__device__ __forceinline__ void cp16(uint32_t dst, const void* src) {
    asm volatile("cp.async.ca.shared.global [%0], [%1], 16;" :: "r"(dst), "l"(src));
}
__device__ __forceinline__ uint32_t packh2(float a, float b) {
    __half2 h = __halves2half2(__float2half_rn(a), __float2half_rn(b));
    return *reinterpret_cast<uint32_t*>(&h);
}
__device__ __forceinline__ uint32_t ford(float f) {   // monotone float->uint
    uint32_t u = __float_as_uint(f);
    return (u & 0x80000000u) ? ~u : (u | 0x80000000u);
}
__device__ __forceinline__ void mma16(float* c, const uint32_t* a, uint32_t b0, uint32_t b1) {
    asm volatile("mma.sync.aligned.m16n8k16.row.col.f32.f16.f16.f32 "
        "{%0,%1,%2,%3},{%4,%5,%6,%7},{%8,%9},{%0,%1,%2,%3};"
        : "+f"(c[0]), "+f"(c[1]), "+f"(c[2]), "+f"(c[3])
        : "r"(a[0]), "r"(a[1]), "r"(a[2]), "r"(a[3]), "r"(b0), "r"(b1));
}

// ================= small kernels =================
__global__ void k_zero() {
    int i = blockIdx.x * blockDim.x + threadIdx.x;
    if (i < KCB * DDIM) g_embed_sum[i] = 0.0f;
    if (i < KCB)        g_counts[i]    = 0.0f;
    if (i < NTOK)       g_keys[i]      = 0xFFFFFFFFFFFFFFFFull;
    if (i == 0) { g_qerr = 0.0f; g_nsum = 0.0f; }
}

__global__ void k_cnorm(const float* __restrict__ w) {
    int warp = (blockIdx.x * blockDim.x + threadIdx.x) >> 5;
    int lane = threadIdx.x & 31;
    if (warp >= KCB) return;
    float v0 = w[warp * DDIM + lane];
    float v1 = w[warp * DDIM + 32 + lane];
    float s = v0 * v0 + v1 * v1;
    #pragma unroll
    for (int o = 16; o; o >>= 1) s += __shfl_xor_sync(0xffffffffu, s, o);
    if (lane == 0) g_cnorm[warp] = s;
}

// build g_w2t: hi pairs (kp<32) and lo pairs (kp>=32), code-contiguous rows
__global__ void k_prep(const float* __restrict__ w) {
    int i = blockIdx.x * blockDim.x + threadIdx.x;
    if (i >= 64 * KCB) return;
    int kp = i >> 13, c = i & (KCB - 1);
    int d = 2 * (kp & 31);
    float x0 = w[(size_t)c * DDIM + d];
    float x1 = w[(size_t)c * DDIM + d + 1];
    float h0 = __half2float(__float2half_rn(x0));
    float h1 = __half2float(__float2half_rn(x1));
    g_w2t[i] = (kp < 32) ? packh2(x0, x1) : packh2(x0 - h0, x1 - h1);
}

// ================= main tensor-core kernel =================
// fp16x3, A-resident, 2 CTAs/SM. Split-K over codes: 4 quarters x 512 token
// tiles = 2048 CTAs, exact merge via packed atomicMin.
static constexpr int AST   = 68;                       // A row stride (uint32)
static constexpr int BST   = 72;                       // B kp-row stride (uint32)
static constexpr int SM_A  = 0;                        // 128*68*4 = 34816
static constexpr int SM_B  = 34816;
static constexpr int B_BUF = 64 * BST * 4;             // 18432
static constexpr int SMEM_TC = SM_B + 3 * B_BUF;       // 90112
static constexpr int QTILES = 32;                      // code-tiles per quarter

__global__ __launch_bounds__(256, 2) void k_main_tc(const float* __restrict__ z) {
    extern __shared__ char smem[];
    uint32_t* Au = (uint32_t*)(smem + SM_A);
    uint32_t* Bu = (uint32_t*)(smem + SM_B);
    const uint32_t sbB = smem_u32(Bu);

    const int tid  = threadIdx.x;
    const int lane = tid & 31, wid = tid >> 5;
    const int g    = lane >> 2, tg = lane & 3;
    const int wr   = wid & 3,  wc = wid >> 2;          // 4 token-rows x 2 code-cols
    const int q    = blockIdx.x >> 9;                  // code quarter
    const int tt   = blockIdx.x & 511;                 // token tile
    const int tok0 = tt * 128;
    const int t0   = q * QTILES;

    // ---- prologue prefetch of B tiles t0, t0+1 ----
    #pragma unroll
    for (int pt = 0; pt < 2; pt++) {
        const uint32_t dstb = sbB + (uint32_t)pt * B_BUF;
        const uint32_t* srcb = g_w2t + (t0 + pt) * 64;
        #pragma unroll
        for (int i = 0; i < 4; i++) {
            int qq = i * 256 + tid;                    // 1024 x 16B
            int kp = qq >> 4, seg = qq & 15;
            cp16(dstb + (uint32_t)(kp * BST + seg * 4) * 4,
                 srcb + (size_t)kp * KCB + seg * 4);
        }
        asm volatile("cp.async.commit_group;");
    }

    // ---- stage A: fp16 split, kp-major: hi kp 0..31, lo kp 32..63 ----
    #pragma unroll
    for (int i = 0; i < 8; i++) {
        int qq = i * 256 + tid;                        // 2048 float4
        int row = qq >> 4, c4 = qq & 15;
        float4 v = *(const float4*)(z + (size_t)(tok0 + row) * DDIM + c4 * 4);
        float hx = __half2float(__float2half_rn(v.x));
        float hy = __half2float(__float2half_rn(v.y));
        float hz = __half2float(__float2half_rn(v.z));
        float hw = __half2float(__float2half_rn(v.w));
        uint32_t* dst = Au + row * AST + 2 * c4;
        dst[0]  = packh2(v.x, v.y);
        dst[1]  = packh2(v.z, v.w);
        dst[32] = packh2(v.x - hx, v.y - hy);
        dst[33] = packh2(v.z - hz, v.w - hw);
    }
    __syncthreads();

    // ---- load ALL A fragments to registers (invariant across tiles) ----
    uint32_t Ah[4][2][4], Al[4][2][4];                 // [j][m][reg]
    {
        const uint32_t* arow = Au + (wr * 32 + g) * AST;
        #pragma unroll
        for (int j = 0; j < 4; j++) {
            #pragma unroll
            for (int m = 0; m < 2; m++) {
                const uint32_t* aph = arow + m * 16 * AST + 8 * j + tg;
                Ah[j][m][0] = aph[0];
                Ah[j][m][1] = aph[8 * AST];
                Ah[j][m][2] = aph[4];
                Ah[j][m][3] = aph[8 * AST + 4];
                const uint32_t* apl = aph + 32;
                Al[j][m][0] = apl[0];
                Al[j][m][1] = apl[8 * AST];
                Al[j][m][2] = apl[4];
                Al[j][m][3] = apl[8 * AST + 4];
            }
        }
    }

    float bv[4];  int bix[4];
    #pragma unroll
    for (int r = 0; r < 4; r++) { bv[r] = 3.4e38f; bix[r] = 0; }

    for (int ti = 0; ti < QTILES; ti++) {
        const int t = t0 + ti;
        if (ti < QTILES - 1) asm volatile("cp.async.wait_group 1;");
        else                 asm volatile("cp.async.wait_group 0;");
        __syncthreads();
        if (ti + 2 < QTILES) {
            const uint32_t dstb = sbB + (uint32_t)((ti + 2) % 3) * B_BUF;
            const uint32_t* srcb = g_w2t + (t + 2) * 64;
            #pragma unroll
            for (int i = 0; i < 4; i++) {
                int qq = i * 256 + tid;
                int kp = qq >> 4, seg = qq & 15;
                cp16(dstb + (uint32_t)(kp * BST + seg * 4) * 4,
                     srcb + (size_t)kp * KCB + seg * 4);
            }
            asm volatile("cp.async.commit_group;");
        }

        const uint32_t* B = Bu + (ti % 3) * (64 * BST);
        float acc[2][4][4];
        #pragma unroll
        for (int m = 0; m < 2; m++)
            #pragma unroll
            for (int nt = 0; nt < 4; nt++)
                #pragma unroll
                for (int c = 0; c < 4; c++) acc[m][nt][c] = 0.0f;

        // per (j,nt): load {bh,bl} once, feed 6 MMAs (zh*wh, zh*wl, zl*wh)
        #pragma unroll
        for (int j = 0; j < 4; j++) {
            const uint32_t* brow = B + (8 * j + tg) * BST + wc * 32 + g;
            #pragma unroll
            for (int nt = 0; nt < 4; nt++) {
                const uint32_t* bph = brow + nt * 8;
                uint32_t bh0 = bph[0];
                uint32_t bh1 = bph[4 * BST];
                uint32_t bl0 = bph[32 * BST];
                uint32_t bl1 = bph[36 * BST];
                mma16(acc[0][nt], Ah[j][0], bh0, bh1);
                mma16(acc[1][nt], Ah[j][1], bh0, bh1);
                mma16(acc[0][nt], Ah[j][0], bl0, bl1);
                mma16(acc[1][nt], Ah[j][1], bl0, bl1);
                mma16(acc[0][nt], Al[j][0], bh0, bh1);
                mma16(acc[1][nt], Al[j][1], bh0, bh1);
            }
        }

        // epilogue: dist = cn - 2*dot, running argmin (ascending codes = first-min)
        const int cb = t * 64;
        #pragma unroll
        for (int nt = 0; nt < 4; nt++) {
            const int col = cb + wc * 32 + nt * 8 + 2 * tg;
            const float2 c2 = __ldg((const float2*)(g_cnorm + col));
            #pragma unroll
            for (int m = 0; m < 2; m++) {
                #pragma unroll
                for (int h = 0; h < 2; h++) {
                    const int r = m * 2 + h;
                    float d0 = fmaf(-2.0f, acc[m][nt][h * 2 + 0], c2.x);
                    float d1 = fmaf(-2.0f, acc[m][nt][h * 2 + 1], c2.y);
                    if (d0 < bv[r]) { bv[r] = d0; bix[r] = col; }
                    if (d1 < bv[r]) { bv[r] = d1; bix[r] = col + 1; }
                }
            }
        }
    }

    // combine across quad lanes (same token rows), tie-break smaller index
    #pragma unroll
    for (int r = 0; r < 4; r++) {
        float v = bv[r]; int ix = bix[r];
        #pragma unroll
        for (int o = 1; o < 4; o <<= 1) {
            float v2 = __shfl_xor_sync(0xffffffffu, v, o);
            int   i2 = __shfl_xor_sync(0xffffffffu, ix, o);
            if (v2 < v || (v2 == v && i2 < ix)) { v = v2; ix = i2; }
        }
        bv[r] = v; bix[r] = ix;
    }
    __syncthreads();
    float* sv = (float*)Bu;
    int*   si = (int*)(Bu + 256);
    if (tg == 0) {
        #pragma unroll
        for (int m = 0; m < 2; m++)
            #pragma unroll
            for (int h = 0; h < 2; h++) {
                int row = wr * 32 + m * 16 + g + 8 * h;
                sv[wc * 128 + row] = bv[m * 2 + h];
                si[wc * 128 + row] = bix[m * 2 + h];
            }
    }
    __syncthreads();
    if (tid < 128) {
        float v0 = sv[tid], v1 = sv[128 + tid];
        int   i0 = si[tid], i1 = si[128 + tid];
        float v = (v1 < v0 || (v1 == v0 && i1 < i0)) ? v1 : v0;
        int  ix = (v1 < v0 || (v1 == v0 && i1 < i0)) ? i1 : i0;
        // exact cross-quarter merge: min dist, then min index on ties
        unsigned long long key = ((unsigned long long)ford(v) << 32) | (uint32_t)ix;
        atomicMin(&g_keys[tok0 + tid], key);
    }
}

// ---------------- scatter: counts, embed_sum, quant error ----------------
__global__ void k_scatter(const float* __restrict__ z, const float* __restrict__ w) {
    __shared__ float qs[8];
    int warp = threadIdx.x >> 5;
    int lane = threadIdx.x & 31;
    int n = blockIdx.x * 8 + warp;
    int k = (int)(g_keys[n] & 0xFFFFFFFFu);
    float z0 = z[(size_t)n * DDIM + lane];
    float z1 = z[(size_t)n * DDIM + 32 + lane];
    float w0 = w[(size_t)k * DDIM + lane];
    float w1 = w[(size_t)k * DDIM + 32 + lane];
    atomicAdd(&g_embed_sum[k * DDIM + lane], z0);
    atomicAdd(&g_embed_sum[k * DDIM + 32 + lane], z1);
    float d0 = w0 - z0, d1 = w1 - z1;
    float s = d0 * d0 + d1 * d1;
    #pragma unroll
    for (int o = 16; o; o >>= 1) s += __shfl_xor_sync(0xffffffffu, s, o);
    if (lane == 0) { qs[warp] = s; atomicAdd(&g_counts[k], 1.0f); }
    __syncthreads();
    if (threadIdx.x == 0) {
        float t = 0.0f;
        #pragma unroll
        for (int i = 0; i < 8; i++) t += qs[i];
        atomicAdd(&g_qerr, t);
    }
}

__global__ void k_ema1(const float* __restrict__ cs, float* __restrict__ out) {
    __shared__ float red[256];
    int k = blockIdx.x * blockDim.x + threadIdx.x;
    float ncs = cs[k] * DECAYF + (1.0f - DECAYF) * g_counts[k];
    out[1 + KCB * DDIM + k] = ncs;
    red[threadIdx.x] = ncs;
    __syncthreads();
    for (int s = 128; s; s >>= 1) {
        if (threadIdx.x < s) red[threadIdx.x] += red[threadIdx.x + s];
        __syncthreads();
    }
    if (threadIdx.x == 0) atomicAdd(&g_nsum, red[0]);
}

__global__ void k_ema2(const float* __restrict__ ea, float* __restrict__ out) {
    int i = blockIdx.x * blockDim.x + threadIdx.x;
    if (i < KCB * DDIM) {
        float nea = ea[i] * DECAYF + (1.0f - DECAYF) * g_embed_sum[i];
        out[1 + KCB * DDIM + KCB + i] = nea;
        int k = i >> 6;
        float ncs = out[1 + KCB * DDIM + k];
        float n = g_nsum;
        float smoothed = (ncs + EPSF) / (n + (float)KCB * EPSF) * n;
        out[1 + i] = nea / smoothed;
    }
    if (i == 0) out[0] = g_qerr / (float)NTOK;
}

extern "C" void kernel_launch(void* const* d_in, const int* in_sizes, int n_in,
                              void* d_out, int out_size) {
    const float* z  = (const float*)d_in[0];
    const float* w  = (const float*)d_in[1];
    const float* cs = (const float*)d_in[2];
    const float* ea = (const float*)d_in[3];
    float* out = (float*)d_out;

    cudaFuncSetAttribute(k_main_tc, cudaFuncAttributeMaxDynamicSharedMemorySize, SMEM_TC);

    k_zero<<<(KCB * DDIM + 255) / 256, 256>>>();
    k_cnorm<<<KCB / 8, 256>>>(w);
    k_prep<<<(64 * KCB + 255) / 256, 256>>>(w);
    k_main_tc<<<4 * (NTOK / 128), 256, SMEM_TC>>>(z);
    k_scatter<<<NTOK / 8, 256>>>(z, w);
    k_ema1<<<KCB / 256, 256>>>(cs, out);
    k_ema2<<<(KCB * DDIM + 255) / 256, 256>>>(ea, out);
}

// round 17
// speedup vs baseline: 1.1771x; 1.0451x over previous
#include <cuda_runtime.h>
#include <cuda_fp16.h>
#include <cstdint>

#define NTOK 65536
#define KCB  8192
#define DDIM 64
#define DECAYF 0.9f
#define EPSF 1e-5f

// ---- scratch (no allocation allowed) ----
__device__ float g_cnorm[KCB];
__device__ unsigned long long g_keys[NTOK];   // packed (ordered dist, code)
__device__ float g_counts[KCB];
__device__ float g_embed_sum[KCB * DDIM];
__device__ float g_qerr;
__device__ float g_nsum;
// pair-major split codebook: g_w2p[tile][pr][col] (uint2)
// pr<16: hi pairs, rows (8j+tg, 8j+tg+4); pr>=16: lo pairs, same rows
__device__ __align__(16) uint2 g_w2p[(size_t)128 * 32 * 64];

// ================= helpers =================
__device__ __forceinline__ uint32_t smem_u32(const void* p) {
    uint32_t a;
    asm("{ .reg .u64 t; cvta.to.shared.u64 t, %1; cvt.u32.u64 %0, t; }" : "=r"(a) : "l"(p));
    return a;
}
__device__ __forceinline__ void cp16(uint32_t dst, const void* src) {
    asm volatile("cp.async.ca.shared.global [%0], [%1], 16;" :: "r"(dst), "l"(src));
}
__device__ __forceinline__ uint32_t packh2(float a, float b) {
    __half2 h = __halves2half2(__float2half_rn(a), __float2half_rn(b));
    return *reinterpret_cast<uint32_t*>(&h);
}
__device__ __forceinline__ uint32_t ford(float f) {   // monotone float->uint
    uint32_t u = __float_as_uint(f);
    return (u & 0x80000000u) ? ~u : (u | 0x80000000u);
}
__device__ __forceinline__ void mma16(float* c, const uint32_t* a, uint32_t b0, uint32_t b1) {
    asm volatile("mma.sync.aligned.m16n8k16.row.col.f32.f16.f16.f32 "
        "{%0,%1,%2,%3},{%4,%5,%6,%7},{%8,%9},{%0,%1,%2,%3};"
        : "+f"(c[0]), "+f"(c[1]), "+f"(c[2]), "+f"(c[3])
        : "r"(a[0]), "r"(a[1]), "r"(a[2]), "r"(a[3]), "r"(b0), "r"(b1));
}

// ================= small kernels =================
__global__ void k_cnorm(const float* __restrict__ w) {
    int warp = (blockIdx.x * blockDim.x + threadIdx.x) >> 5;
    int lane = threadIdx.x & 31;
    if (warp >= KCB) return;
    float v0 = w[warp * DDIM + lane];
    float v1 = w[warp * DDIM + 32 + lane];
    float s = v0 * v0 + v1 * v1;
    #pragma unroll
    for (int o = 16; o; o >>= 1) s += __shfl_xor_sync(0xffffffffu, s, o);
    if (lane == 0) g_cnorm[warp] = s;
}

// build g_w2p (pair-major, KCB*32 entries) + fold in all zero-init
__global__ void k_prep(const float* __restrict__ w) {
    int i = blockIdx.x * blockDim.x + threadIdx.x;
    if (i >= KCB * 64) return;
    // zero-init folded in (needs KCB*64 threads)
    g_embed_sum[i] = 0.0f;
    if (i < KCB)  g_counts[i] = 0.0f;
    if (i < NTOK) g_keys[i]   = 0xFFFFFFFFFFFFFFFFull;
    if (i == 0) { g_qerr = 0.0f; g_nsum = 0.0f; }

    if (i >= KCB * 32) return;                  // w2p has KCB*32 uint2 entries
    int col = i & 63, pr = (i >> 6) & 31, t = i >> 11;   // t in [0,128)
    int jj = (pr & 15) >> 2, tgg = pr & 3;
    int k0 = 8 * jj + tgg, k1 = k0 + 4;
    int code = t * 64 + col;
    float a0 = w[(size_t)code * DDIM + 2 * k0];
    float a1 = w[(size_t)code * DDIM + 2 * k0 + 1];
    float b0 = w[(size_t)code * DDIM + 2 * k1];
    float b1 = w[(size_t)code * DDIM + 2 * k1 + 1];
    uint2 val;
    if (pr < 16) {
        val.x = packh2(a0, a1);
        val.y = packh2(b0, b1);
    } else {
        float ha0 = __half2float(__float2half_rn(a0));
        float ha1 = __half2float(__float2half_rn(a1));
        float hb0 = __half2float(__float2half_rn(b0));
        float hb1 = __half2float(__float2half_rn(b1));
        val.x = packh2(a0 - ha0, a1 - ha1);
        val.y = packh2(b0 - hb0, b1 - hb1);
    }
    g_w2p[((size_t)t * 32 + pr) * 64 + col] = val;
}

// ================= main tensor-core kernel =================
// fp16x3, A-resident, 2 CTAs/SM, split-K over 4 code quarters, LDS.64 B frags.
static constexpr int AST   = 68;                       // A row stride (uint32)
static constexpr int ST2   = 68;                       // B pair-row stride (uint2)
static constexpr int SM_A  = 0;                        // 128*68*4 = 34816
static constexpr int SM_B  = 34816;
static constexpr int B_BUF = 32 * ST2 * 8;             // 17408 bytes
static constexpr int SMEM_TC = SM_B + 3 * B_BUF;       // 87040
static constexpr int QTILES = 32;                      // code-tiles per quarter

__global__ __launch_bounds__(256, 2) void k_main_tc(const float* __restrict__ z) {
    extern __shared__ char smem[];
    uint32_t* Au = (uint32_t*)(smem + SM_A);
    uint2*    Bu = (uint2*)(smem + SM_B);
    const uint32_t sbB = smem_u32(Bu);

    const int tid  = threadIdx.x;
    const int lane = tid & 31, wid = tid >> 5;
    const int g    = lane >> 2, tg = lane & 3;
    const int wr   = wid & 3,  wc = wid >> 2;          // 4 token-rows x 2 code-cols
    const int q    = blockIdx.x >> 9;                  // code quarter
    const int tt   = blockIdx.x & 511;                 // token tile
    const int tok0 = tt * 128;
    const int t0   = q * QTILES;

    // ---- prologue prefetch of B tiles t0, t0+1 ----
    #pragma unroll
    for (int pt = 0; pt < 2; pt++) {
        const uint32_t dstb = sbB + (uint32_t)pt * B_BUF;
        const uint2* srcb = g_w2p + (size_t)(t0 + pt) * 32 * 64;
        #pragma unroll
        for (int i = 0; i < 4; i++) {
            int qq = i * 256 + tid;                    // 1024 x 16B chunks
            int pr = qq >> 5, cp = qq & 31;            // 32 chunks per pair-row
            cp16(dstb + (uint32_t)(pr * ST2 * 8 + cp * 16),
                 srcb + (size_t)pr * 64 + cp * 2);
        }
        asm volatile("cp.async.commit_group;");
    }

    // ---- stage A: fp16 split, kp-major: hi kp 0..31, lo kp 32..63 ----
    #pragma unroll
    for (int i = 0; i < 8; i++) {
        int qq = i * 256 + tid;                        // 2048 float4
        int row = qq >> 4, c4 = qq & 15;
        float4 v = *(const float4*)(z + (size_t)(tok0 + row) * DDIM + c4 * 4);
        float hx = __half2float(__float2half_rn(v.x));
        float hy = __half2float(__float2half_rn(v.y));
        float hz = __half2float(__float2half_rn(v.z));
        float hw = __half2float(__float2half_rn(v.w));
        uint32_t* dst = Au + row * AST + 2 * c4;
        dst[0]  = packh2(v.x, v.y);
        dst[1]  = packh2(v.z, v.w);
        dst[32] = packh2(v.x - hx, v.y - hy);
        dst[33] = packh2(v.z - hz, v.w - hw);
    }
    __syncthreads();

    // ---- load ALL A fragments to registers (invariant across tiles) ----
    uint32_t Ah[4][2][4], Al[4][2][4];                 // [j][m][reg]
    {
        const uint32_t* arow = Au + (wr * 32 + g) * AST;
        #pragma unroll
        for (int j = 0; j < 4; j++) {
            #pragma unroll
            for (int m = 0; m < 2; m++) {
                const uint32_t* aph = arow + m * 16 * AST + 8 * j + tg;
                Ah[j][m][0] = aph[0];
                Ah[j][m][1] = aph[8 * AST];
                Ah[j][m][2] = aph[4];
                Ah[j][m][3] = aph[8 * AST + 4];
                const uint32_t* apl = aph + 32;
                Al[j][m][0] = apl[0];
                Al[j][m][1] = apl[8 * AST];
                Al[j][m][2] = apl[4];
                Al[j][m][3] = apl[8 * AST + 4];
            }
        }
    }

    float bv[4];  int bix[4];
    #pragma unroll
    for (int r = 0; r < 4; r++) { bv[r] = 3.4e38f; bix[r] = 0; }

    for (int ti = 0; ti < QTILES; ti++) {
        const int t = t0 + ti;
        if (ti < QTILES - 1) asm volatile("cp.async.wait_group 1;");
        else                 asm volatile("cp.async.wait_group 0;");
        __syncthreads();
        if (ti + 2 < QTILES) {
            const uint32_t dstb = sbB + (uint32_t)((ti + 2) % 3) * B_BUF;
            const uint2* srcb = g_w2p + (size_t)(t + 2) * 32 * 64;
            #pragma unroll
            for (int i = 0; i < 4; i++) {
                int qq = i * 256 + tid;
                int pr = qq >> 5, cp = qq & 31;
                cp16(dstb + (uint32_t)(pr * ST2 * 8 + cp * 16),
                     srcb + (size_t)pr * 64 + cp * 2);
            }
            asm volatile("cp.async.commit_group;");
        }

        const uint2* B = Bu + (ti % 3) * (32 * ST2);
        float acc[2][4][4];
        #pragma unroll
        for (int m = 0; m < 2; m++)
            #pragma unroll
            for (int nt = 0; nt < 4; nt++)
                #pragma unroll
                for (int c = 0; c < 4; c++) acc[m][nt][c] = 0.0f;

        // per (j,nt): 2x LDS.64 {hi pair, lo pair}, feed 6 MMAs
        #pragma unroll
        for (int j = 0; j < 4; j++) {
            const uint2* brow = B + (4 * j + tg) * ST2 + wc * 32 + g;
            #pragma unroll
            for (int nt = 0; nt < 4; nt++) {
                uint2 bh = brow[nt * 8];
                uint2 bl = brow[16 * ST2 + nt * 8];
                mma16(acc[0][nt], Ah[j][0], bh.x, bh.y);
                mma16(acc[1][nt], Ah[j][1], bh.x, bh.y);
                mma16(acc[0][nt], Ah[j][0], bl.x, bl.y);
                mma16(acc[1][nt], Ah[j][1], bl.x, bl.y);
                mma16(acc[0][nt], Al[j][0], bh.x, bh.y);
                mma16(acc[1][nt], Al[j][1], bh.x, bh.y);
            }
        }

        // epilogue: dist = cn - 2*dot, running argmin (ascending codes = first-min)
        const int cb = t * 64;
        #pragma unroll
        for (int nt = 0; nt < 4; nt++) {
            const int col = cb + wc * 32 + nt * 8 + 2 * tg;
            const float2 c2 = __ldg((const float2*)(g_cnorm + col));
            #pragma unroll
            for (int m = 0; m < 2; m++) {
                #pragma unroll
                for (int h = 0; h < 2; h++) {
                    const int r = m * 2 + h;
                    float d0 = fmaf(-2.0f, acc[m][nt][h * 2 + 0], c2.x);
                    float d1 = fmaf(-2.0f, acc[m][nt][h * 2 + 1], c2.y);
                    if (d0 < bv[r]) { bv[r] = d0; bix[r] = col; }
                    if (d1 < bv[r]) { bv[r] = d1; bix[r] = col + 1; }
                }
            }
        }
    }

    // combine across quad lanes (same token rows), tie-break smaller index
    #pragma unroll
    for (int r = 0; r < 4; r++) {
        float v = bv[r]; int ix = bix[r];
        #pragma unroll
        for (int o = 1; o < 4; o <<= 1) {
            float v2 = __shfl_xor_sync(0xffffffffu, v, o);
            int   i2 = __shfl_xor_sync(0xffffffffu, ix, o);
            if (v2 < v || (v2 == v && i2 < ix)) { v = v2; ix = i2; }
        }
        bv[r] = v; bix[r] = ix;
    }
    __syncthreads();
    float* sv = (float*)Bu;
    int*   si = (int*)((char*)Bu + 1024);
    if (tg == 0) {
        #pragma unroll
        for (int m = 0; m < 2; m++)
            #pragma unroll
            for (int h = 0; h < 2; h++) {
                int row = wr * 32 + m * 16 + g + 8 * h;
                sv[wc * 128 + row] = bv[m * 2 + h];
                si[wc * 128 + row] = bix[m * 2 + h];
            }
    }
    __syncthreads();
    if (tid < 128) {
        float v0 = sv[tid], v1 = sv[128 + tid];
        int   i0 = si[tid], i1 = si[128 + tid];
        float v = (v1 < v0 || (v1 == v0 && i1 < i0)) ? v1 : v0;
        int  ix = (v1 < v0 || (v1 == v0 && i1 < i0)) ? i1 : i0;
        // exact cross-quarter merge: min dist, then min index on ties
        unsigned long long key = ((unsigned long long)ford(v) << 32) | (uint32_t)ix;
        atomicMin(&g_keys[tok0 + tid], key);
    }
}

// ---------------- scatter: counts, embed_sum, quant error ----------------
__global__ void k_scatter(const float* __restrict__ z, const float* __restrict__ w) {
    __shared__ float qs[8];
    int warp = threadIdx.x >> 5;
    int lane = threadIdx.x & 31;
    int n = blockIdx.x * 8 + warp;
    int k = (int)(g_keys[n] & 0xFFFFFFFFu);
    float z0 = z[(size_t)n * DDIM + lane];
    float z1 = z[(size_t)n * DDIM + 32 + lane];
    float w0 = w[(size_t)k * DDIM + lane];
    float w1 = w[(size_t)k * DDIM + 32 + lane];
    atomicAdd(&g_embed_sum[k * DDIM + lane], z0);
    atomicAdd(&g_embed_sum[k * DDIM + 32 + lane], z1);
    float d0 = w0 - z0, d1 = w1 - z1;
    float s = d0 * d0 + d1 * d1;
    #pragma unroll
    for (int o = 16; o; o >>= 1) s += __shfl_xor_sync(0xffffffffu, s, o);
    if (lane == 0) { qs[warp] = s; atomicAdd(&g_counts[k], 1.0f); }
    __syncthreads();
    if (threadIdx.x == 0) {
        float t = 0.0f;
        #pragma unroll
        for (int i = 0; i < 8; i++) t += qs[i];
        atomicAdd(&g_qerr, t);
    }
}

__global__ void k_ema1(const float* __restrict__ cs, float* __restrict__ out) {
    __shared__ float red[256];
    int k = blockIdx.x * blockDim.x + threadIdx.x;
    float ncs = cs[k] * DECAYF + (1.0f - DECAYF) * g_counts[k];
    out[1 + KCB * DDIM + k] = ncs;
    red[threadIdx.x] = ncs;
    __syncthreads();
    for (int s = 128; s; s >>= 1) {
        if (threadIdx.x < s) red[threadIdx.x] += red[threadIdx.x + s];
        __syncthreads();
    }
    if (threadIdx.x == 0) atomicAdd(&g_nsum, red[0]);
}

__global__ void k_ema2(const float* __restrict__ ea, float* __restrict__ out) {
    int i = blockIdx.x * blockDim.x + threadIdx.x;
    if (i < KCB * DDIM) {
        float nea = ea[i] * DECAYF + (1.0f - DECAYF) * g_embed_sum[i];
        out[1 + KCB * DDIM + KCB + i] = nea;
        int k = i >> 6;
        float ncs = out[1 + KCB * DDIM + k];
        float n = g_nsum;
        float smoothed = (ncs + EPSF) / (n + (float)KCB * EPSF) * n;
        out[1 + i] = nea / smoothed;
    }
    if (i == 0) out[0] = g_qerr / (float)NTOK;
}

extern "C" void kernel_launch(void* const* d_in, const int* in_sizes, int n_in,
                              void* d_out, int out_size) {
    const float* z  = (const float*)d_in[0];
    const float* w  = (const float*)d_in[1];
    const float* cs = (const float*)d_in[2];
    const float* ea = (const float*)d_in[3];
    float* out = (float*)d_out;

    cudaFuncSetAttribute(k_main_tc, cudaFuncAttributeMaxDynamicSharedMemorySize, SMEM_TC);

    k_cnorm<<<KCB / 8, 256>>>(w);
    k_prep<<<(KCB * 64 + 255) / 256, 256>>>(w);
    k_main_tc<<<4 * (NTOK / 128), 256, SMEM_TC>>>(z);
    k_scatter<<<NTOK / 8, 256>>>(z, w);
    k_ema1<<<KCB / 256, 256>>>(cs, out);
    k_ema2<<<(KCB * DDIM + 255) / 256, 256>>>(ea, out);
}